// round 1
// baseline (speedup 1.0000x reference)
#include <cuda_runtime.h>
#include <cstdint>

// ---------------------------------------------------------------------------
// GCN: out = head(meanpool(gcn2(gcn1(x))))
//
// Restructuring:
//   gcn_conv(x,W,b)[d] = dinv[d]*( sum_{e:dst=d} p[src_e] + p[d] ) + b,
//       where p = (x @ W) * dinv  (rowwise),  dinv = rsqrt(1+deg_dst)
//   Layer2 aggregation commutes with @W2, and so does mean pooling, so W2 is
//   applied to the pooled [G,32] tensor inside the head kernel.
// ---------------------------------------------------------------------------

#define MAXN 100000
#define MAXE 1600000
#define MAXG 256
#define C 32          // hidden width carried through both scatters

__device__ int   g_src[MAXE];
__device__ int   g_dst[MAXE];
__device__ int   g_deg[MAXN];
__device__ float g_dinv[MAXN];
__device__ float g_p[MAXN * C];     // p1, overwritten in-place with q (layer2 input)
__device__ float g_acc[MAXN * C];   // scatter accumulator (zeroed per layer)
__device__ float g_pool[MAXG * C];  // pooled mean of layer-2 aggregate (pre-W2)
__device__ int   g_flags[2];        // [0]=edge_index is int64, [1]=batch is int64

static inline int ceil_div(int a, int b) { return (a + b - 1) / b; }

// ---------------------------------------------------------------------------
// dtype detection: for little-endian positive int64, every odd 32-bit word is
// zero. Sample 4096 odd words spread across the buffer; OR them.
// ---------------------------------------------------------------------------
__global__ void k_detect(const unsigned* __restrict__ e, long ewords,
                         const unsigned* __restrict__ b, long bwords) {
    __shared__ unsigned se, sb;
    if (threadIdx.x == 0) { se = 0u; sb = 0u; }
    __syncthreads();
    unsigned a = 0u, c = 0u;
    long eh = ewords / 2, bh = bwords / 2;
    for (int s = 0; s < 16; s++) {
        long idx = (long)(threadIdx.x * 16 + s);
        long j = (idx * eh) / 4096;            // j in [0, eh)
        a |= e[2 * j + 1];                      // < ewords: safe for both dtypes
        long k = (idx * bh) / 4096;
        c |= b[2 * k + 1];
    }
    atomicOr(&se, a);
    atomicOr(&sb, c);
    __syncthreads();
    if (threadIdx.x == 0) {
        g_flags[0] = (se == 0u) ? 1 : 0;
        g_flags[1] = (sb == 0u) ? 1 : 0;
    }
}

__device__ __forceinline__ int idx_get(const void* p, long i, int is64) {
    return is64 ? (int)((const long long*)p)[i] : ((const int*)p)[i];
}

// ---------------------------------------------------------------------------
// Convert edge_index to int32 + degree count (deg over dst, self-loop adds 1)
// ---------------------------------------------------------------------------
__global__ void k_convert(const void* __restrict__ eidx, int E) {
    int e = blockIdx.x * blockDim.x + threadIdx.x;
    if (e >= E) return;
    int is64 = g_flags[0];
    int s = idx_get(eidx, e, is64);
    int t = idx_get(eidx, (long)E + e, is64);
    g_src[e] = s;
    g_dst[e] = t;
    atomicAdd(&g_deg[t], 1);
}

__global__ void k_dinv(int N) {
    int n = blockIdx.x * blockDim.x + threadIdx.x;
    if (n >= N) return;
    g_dinv[n] = rsqrtf(1.0f + (float)g_deg[n]);
}

// ---------------------------------------------------------------------------
// GEMM1: p[n,:] = dinv[n] * (x[n,:] @ W1)   (100k x 128 x 32)
// W1 staged in smem, broadcast float4 reads; 1 node per thread.
// ---------------------------------------------------------------------------
__global__ void k_gemm1(const float* __restrict__ x,
                        const float* __restrict__ W1, int N) {
    __shared__ float sW[128 * C];
    for (int i = threadIdx.x; i < 128 * C; i += blockDim.x) sW[i] = W1[i];
    __syncthreads();

    int n = blockIdx.x * blockDim.x + threadIdx.x;
    if (n >= N) return;

    float acc[C];
#pragma unroll
    for (int j = 0; j < C; j++) acc[j] = 0.0f;

    const float4* xr = (const float4*)(x + (size_t)n * 128);
#pragma unroll 4
    for (int k4 = 0; k4 < 32; k4++) {
        float4 xv = __ldg(&xr[k4]);
        const float* xf = (const float*)&xv;
#pragma unroll
        for (int kk = 0; kk < 4; kk++) {
            float xk = xf[kk];
            const float4* wr = (const float4*)(sW + (k4 * 4 + kk) * C);
#pragma unroll
            for (int j4 = 0; j4 < C / 4; j4++) {
                float4 w = wr[j4];
                acc[j4 * 4 + 0] = fmaf(xk, w.x, acc[j4 * 4 + 0]);
                acc[j4 * 4 + 1] = fmaf(xk, w.y, acc[j4 * 4 + 1]);
                acc[j4 * 4 + 2] = fmaf(xk, w.z, acc[j4 * 4 + 2]);
                acc[j4 * 4 + 3] = fmaf(xk, w.w, acc[j4 * 4 + 3]);
            }
        }
    }
    float di = g_dinv[n];
    float4* out = (float4*)(g_p + (size_t)n * C);
#pragma unroll
    for (int j4 = 0; j4 < C / 4; j4++) {
        out[j4] = make_float4(acc[j4 * 4 + 0] * di, acc[j4 * 4 + 1] * di,
                              acc[j4 * 4 + 2] * di, acc[j4 * 4 + 3] * di);
    }
}

// ---------------------------------------------------------------------------
// Scatter: acc[dst,:] += p[src,:]  (32 floats/edge via 8x red.v4.f32)
// ---------------------------------------------------------------------------
__device__ __forceinline__ void red_add_v4(float* ptr, float4 v) {
    asm volatile("red.global.add.v4.f32 [%0], {%1, %2, %3, %4};"
                 :: "l"(ptr), "f"(v.x), "f"(v.y), "f"(v.z), "f"(v.w)
                 : "memory");
}

__global__ void k_scatter(int E) {
    int e = blockIdx.x * blockDim.x + threadIdx.x;
    if (e >= E) return;
    int s = g_src[e];
    int t = g_dst[e];
    const float4* sp = (const float4*)(g_p + (size_t)s * C);
    float* tp = g_acc + (size_t)t * C;
#pragma unroll
    for (int i = 0; i < C / 4; i++) {
        float4 v = __ldg(&sp[i]);
        red_add_v4(tp + i * 4, v);
    }
}

// ---------------------------------------------------------------------------
// Between layers: q[n] = dinv[n] * ( dinv[n]*(acc[n]+p[n]) + b1 ), in place.
// (out1 = dinv*(sum+p1)+b1; q = out1*dinv is the layer-2 pre-scaled input)
// ---------------------------------------------------------------------------
__global__ void k_between(const float* __restrict__ b1, int N) {
    int i = blockIdx.x * blockDim.x + threadIdx.x;  // one float4 chunk
    if (i >= N * (C / 4)) return;
    int n = i >> 3;
    int c = i & 7;
    float di = g_dinv[n];
    float4 a = ((const float4*)g_acc)[i];
    float4 p = ((const float4*)g_p)[i];
    float4 b = ((const float4*)b1)[c];
    float4 q;
    q.x = di * (di * (a.x + p.x) + b.x);
    q.y = di * (di * (a.y + p.y) + b.y);
    q.z = di * (di * (a.z + p.z) + b.z);
    q.w = di * (di * (a.w + p.w) + b.w);
    ((float4*)g_p)[i] = q;
}

// ---------------------------------------------------------------------------
// Pool: per graph g (one block), binary-search its contiguous node range in
// sorted batch, then pool[g,j] = mean_n dinv[n]*(acc[n,j]+q[n,j]).
// ---------------------------------------------------------------------------
__global__ void k_pool(const void* __restrict__ batch, int N, int G) {
    int g = blockIdx.x;
    int is64 = g_flags[1];

    // lower_bound(batch, g) and lower_bound(batch, g+1)
    int lo = 0, hi = N;
    while (lo < hi) { int m = (lo + hi) >> 1; if (idx_get(batch, m, is64) < g) lo = m + 1; else hi = m; }
    int start = lo;
    hi = N;
    while (lo < hi) { int m = (lo + hi) >> 1; if (idx_get(batch, m, is64) < g + 1) lo = m + 1; else hi = m; }
    int end = lo;

    int j = threadIdx.x & 31;
    int row = threadIdx.x >> 5;   // 8 node-lanes
    float sum = 0.0f;
    for (int n = start + row; n < end; n += 8) {
        float di = g_dinv[n];
        sum += di * (g_acc[(size_t)n * C + j] + g_p[(size_t)n * C + j]);
    }
    __shared__ float red[256];
    red[threadIdx.x] = sum;
    __syncthreads();
    if (threadIdx.x < C) {
        float tot = 0.0f;
#pragma unroll
        for (int r = 0; r < 8; r++) tot += red[r * 32 + j];
        int cnt = end - start;
        g_pool[g * C + j] = tot / (float)max(cnt, 1);
    }
}

// ---------------------------------------------------------------------------
// Head (single block, one thread per graph):
//   o2 = pool @ W2 + b2 ; z = relu(o2 @ fcW1 + fcb1) ; batchnorm(z) over G ;
//   out = softplus(z_bn @ fcW2 + fcb2)
// ---------------------------------------------------------------------------
__global__ void k_head(const float* __restrict__ W2, const float* __restrict__ b2,
                       const float* __restrict__ fcW1, const float* __restrict__ fcb1,
                       const float* __restrict__ gamma, const float* __restrict__ beta,
                       const float* __restrict__ fcW2, const float* __restrict__ fcb2,
                       float* __restrict__ out, int G) {
    __shared__ float sW2[32 * 64];
    __shared__ float sF1[64 * 32];
    __shared__ float sb2[64], sfb1[32], sgam[32], sbet[32], sfw2[32];
    __shared__ float ssum[32], ssq[32];
    __shared__ float sfb2;

    int tid = threadIdx.x;
    for (int i = tid; i < 32 * 64; i += blockDim.x) sW2[i] = W2[i];
    for (int i = tid; i < 64 * 32; i += blockDim.x) sF1[i] = fcW1[i];
    if (tid < 64) sb2[tid] = b2[tid];
    if (tid < 32) {
        sfb1[tid] = fcb1[tid]; sgam[tid] = gamma[tid]; sbet[tid] = beta[tid];
        sfw2[tid] = fcW2[tid]; ssum[tid] = 0.0f; ssq[tid] = 0.0f;
    }
    if (tid == 0) sfb2 = fcb2[0];
    __syncthreads();

    int g = tid;  // blockDim == G
    float r[32];
#pragma unroll
    for (int i = 0; i < 32; i++) r[i] = g_pool[g * 32 + i];

    float o2[64];
#pragma unroll
    for (int j = 0; j < 64; j++) o2[j] = sb2[j];
    for (int k = 0; k < 32; k++) {
        float rk = r[k];
#pragma unroll
        for (int j = 0; j < 64; j++) o2[j] = fmaf(rk, sW2[k * 64 + j], o2[j]);
    }

    float z[32];
#pragma unroll
    for (int i = 0; i < 32; i++) z[i] = sfb1[i];
    for (int j = 0; j < 64; j++) {
        float oj = o2[j];
#pragma unroll
        for (int i = 0; i < 32; i++) z[i] = fmaf(oj, sF1[j * 32 + i], z[i]);
    }
#pragma unroll
    for (int i = 0; i < 32; i++) z[i] = fmaxf(z[i], 0.0f);

    // batch stats: warp shuffle reduce, then one smem atomic per warp
    for (int i = 0; i < 32; i++) {
        float v = z[i], v2 = v * v;
#pragma unroll
        for (int o = 16; o > 0; o >>= 1) {
            v += __shfl_down_sync(0xFFFFFFFFu, v, o);
            v2 += __shfl_down_sync(0xFFFFFFFFu, v2, o);
        }
        if ((tid & 31) == 0) { atomicAdd(&ssum[i], v); atomicAdd(&ssq[i], v2); }
    }
    __syncthreads();

    float acc = sfb2;
    float invG = 1.0f / (float)G;
#pragma unroll
    for (int i = 0; i < 32; i++) {
        float mu = ssum[i] * invG;
        float var = ssq[i] * invG - mu * mu;
        float zb = (z[i] - mu) * rsqrtf(var + 1e-5f) * sgam[i] + sbet[i];
        acc = fmaf(zb, sfw2[i], acc);
    }
    // stable softplus = max(x,0) + log1p(exp(-|x|))
    out[g] = fmaxf(acc, 0.0f) + log1pf(expf(-fabsf(acc)));
}

// ---------------------------------------------------------------------------
extern "C" void kernel_launch(void* const* d_in, const int* in_sizes, int n_in,
                              void* d_out, int out_size) {
    const float* x     = (const float*)d_in[0];
    const void*  eidx  = d_in[1];
    const void*  batch = d_in[2];
    const float* W1    = (const float*)d_in[3];
    const float* b1    = (const float*)d_in[4];
    const float* W2    = (const float*)d_in[5];
    const float* b2    = (const float*)d_in[6];
    const float* fcW1  = (const float*)d_in[7];
    const float* fcb1  = (const float*)d_in[8];
    const float* gamma = (const float*)d_in[9];
    const float* beta  = (const float*)d_in[10];
    const float* fcW2  = (const float*)d_in[11];
    const float* fcb2  = (const float*)d_in[12];

    int N = in_sizes[0] / 128;
    int E = in_sizes[1] / 2;
    int G = out_size;

    void *pdeg, *pacc;
    cudaGetSymbolAddress(&pdeg, g_deg);
    cudaGetSymbolAddress(&pacc, g_acc);

    cudaMemsetAsync(pdeg, 0, (size_t)N * sizeof(int));
    cudaMemsetAsync(pacc, 0, (size_t)N * C * sizeof(float));

    k_detect<<<1, 256>>>((const unsigned*)eidx, (long)2 * E,
                         (const unsigned*)batch, (long)N);
    k_convert<<<ceil_div(E, 256), 256>>>(eidx, E);
    k_dinv<<<ceil_div(N, 256), 256>>>(N);
    k_gemm1<<<ceil_div(N, 256), 256>>>(x, W1, N);
    k_scatter<<<ceil_div(E, 256), 256>>>(E);
    k_between<<<ceil_div(N * (C / 4), 256), 256>>>(b1, N);
    cudaMemsetAsync(pacc, 0, (size_t)N * C * sizeof(float));
    k_scatter<<<ceil_div(E, 256), 256>>>(E);
    k_pool<<<G, 256>>>(batch, N, G);
    k_head<<<1, G>>>(W2, b2, fcW1, fcb1, gamma, beta, fcW2, fcb2,
                     (float*)d_out, G);
}